// round 3
// baseline (speedup 1.0000x reference)
#include <cuda_runtime.h>

#define BATCH   4
#define SEQ     512
#define DMODEL  512
#define MROWS   (BATCH * SEQ)       // 2048
#define NHEADS  64                  // "head" axis = d_k in this module
#define HDIM    8                   // per-head feature dim

// ---------------------------------------------------------------------------
// Scratch (no cudaMalloc allowed)
// ---------------------------------------------------------------------------
__device__ float g_qn[MROWS * DMODEL];
__device__ float g_Qp[MROWS * DMODEL];
__device__ float g_Kp[MROWS * DMODEL];
__device__ float g_Vp[MROWS * DMODEL];
__device__ float g_Qc[MROWS * DMODEL];   // packed [bd][t][8]
__device__ float g_Kc[MROWS * DMODEL];
__device__ float g_Vc[MROWS * DMODEL];
__device__ float g_Oc[MROWS * DMODEL];   // packed attention output

// ---------------------------------------------------------------------------
// LayerNorm over last dim (512), one block per row
// ---------------------------------------------------------------------------
__global__ __launch_bounds__(256) void ln_kernel(
    const float* __restrict__ x, const float* __restrict__ gamma,
    const float* __restrict__ beta, float* __restrict__ out)
{
    int row = blockIdx.x;
    const float* xr = x + (size_t)row * DMODEL;
    int tid = threadIdx.x;
    float a0 = xr[tid];
    float a1 = xr[tid + 256];

    __shared__ float red[8];
    __shared__ float red2[8];
    int warp = tid >> 5, lane = tid & 31;

    float s = a0 + a1;
    #pragma unroll
    for (int o = 16; o; o >>= 1) s += __shfl_xor_sync(0xffffffffu, s, o);
    if (lane == 0) red[warp] = s;
    __syncthreads();
    float mean = (red[0] + red[1] + red[2] + red[3] +
                  red[4] + red[5] + red[6] + red[7]) * (1.0f / 512.0f);

    float d0 = a0 - mean, d1 = a1 - mean;
    float vs = d0 * d0 + d1 * d1;
    #pragma unroll
    for (int o = 16; o; o >>= 1) vs += __shfl_xor_sync(0xffffffffu, vs, o);
    if (lane == 0) red2[warp] = vs;
    __syncthreads();
    float var = (red2[0] + red2[1] + red2[2] + red2[3] +
                 red2[4] + red2[5] + red2[6] + red2[7]) * (1.0f / 512.0f);
    float inv = rsqrtf(var + 1e-6f);

    float* orow = out + (size_t)row * DMODEL;
    orow[tid]       = d0 * inv * gamma[tid]       + beta[tid];
    orow[tid + 256] = d1 * inv * gamma[tid + 256] + beta[tid + 256];
}

// ---------------------------------------------------------------------------
// Batched QKV SGEMM: C[z][2048,512] = A[z] @ W[z]^T
// 128x64 tile, BK=16, 256 threads, double-buffered smem, reg-staged loads.
// ---------------------------------------------------------------------------
__global__ __launch_bounds__(256, 3) void sgemm_qkv(
    const float* __restrict__ A0, const float* __restrict__ A1,
    const float* __restrict__ A2,
    const float* __restrict__ W0, const float* __restrict__ W1,
    const float* __restrict__ W2,
    float* __restrict__ C0, float* __restrict__ C1, float* __restrict__ C2)
{
    const int K = DMODEL;
    __shared__ float As[2][16][128];
    __shared__ float Bs[2][16][64];

    int z = blockIdx.z;
    const float* A = (z == 0) ? A0 : (z == 1) ? A1 : A2;
    const float* W = (z == 0) ? W0 : (z == 1) ? W1 : W2;
    float*       C = (z == 0) ? C0 : (z == 1) ? C1 : C2;

    int bm = blockIdx.y * 128;
    int bn = blockIdx.x * 64;
    int tid = threadIdx.x;
    int tx = tid & 15;
    int ty = tid >> 4;

    // load geometry
    int ar0 = tid >> 2,         ac0 = (tid & 3) << 2;          // A idx0
    int ar1 = (tid + 256) >> 2, ac1 = ac0;                      // A idx1
    int br  = tid >> 2,         bc  = (tid & 3) << 2;           // W idx

    float acc[8][4];
    #pragma unroll
    for (int i = 0; i < 8; i++)
        #pragma unroll
        for (int j = 0; j < 4; j++) acc[i][j] = 0.0f;

    float4 ra0, ra1, rb;
    // prologue: chunk 0 -> buf0
    ra0 = *(const float4*)(A + (size_t)(bm + ar0) * K + ac0);
    ra1 = *(const float4*)(A + (size_t)(bm + ar1) * K + ac1);
    rb  = *(const float4*)(W + (size_t)(bn + br)  * K + bc);
    As[0][ac0 + 0][ar0] = ra0.x; As[0][ac0 + 1][ar0] = ra0.y;
    As[0][ac0 + 2][ar0] = ra0.z; As[0][ac0 + 3][ar0] = ra0.w;
    As[0][ac1 + 0][ar1] = ra1.x; As[0][ac1 + 1][ar1] = ra1.y;
    As[0][ac1 + 2][ar1] = ra1.z; As[0][ac1 + 3][ar1] = ra1.w;
    Bs[0][bc + 0][br] = rb.x; Bs[0][bc + 1][br] = rb.y;
    Bs[0][bc + 2][br] = rb.z; Bs[0][bc + 3][br] = rb.w;
    // stage chunk 1
    ra0 = *(const float4*)(A + (size_t)(bm + ar0) * K + 16 + ac0);
    ra1 = *(const float4*)(A + (size_t)(bm + ar1) * K + 16 + ac1);
    rb  = *(const float4*)(W + (size_t)(bn + br)  * K + 16 + bc);
    __syncthreads();

    const int NCH = K / 16;   // 32
    for (int c = 0; c < NCH; c++) {
        int cur = c & 1, nxt = cur ^ 1;
        if (c + 1 < NCH) {
            As[nxt][ac0 + 0][ar0] = ra0.x; As[nxt][ac0 + 1][ar0] = ra0.y;
            As[nxt][ac0 + 2][ar0] = ra0.z; As[nxt][ac0 + 3][ar0] = ra0.w;
            As[nxt][ac1 + 0][ar1] = ra1.x; As[nxt][ac1 + 1][ar1] = ra1.y;
            As[nxt][ac1 + 2][ar1] = ra1.z; As[nxt][ac1 + 3][ar1] = ra1.w;
            Bs[nxt][bc + 0][br] = rb.x; Bs[nxt][bc + 1][br] = rb.y;
            Bs[nxt][bc + 2][br] = rb.z; Bs[nxt][bc + 3][br] = rb.w;
        }
        if (c + 2 < NCH) {
            int k0 = (c + 2) * 16;
            ra0 = *(const float4*)(A + (size_t)(bm + ar0) * K + k0 + ac0);
            ra1 = *(const float4*)(A + (size_t)(bm + ar1) * K + k0 + ac1);
            rb  = *(const float4*)(W + (size_t)(bn + br)  * K + k0 + bc);
        }
        #pragma unroll
        for (int kk = 0; kk < 16; kk++) {
            float4 a0 = *(const float4*)&As[cur][kk][ty * 8];
            float4 a1 = *(const float4*)&As[cur][kk][ty * 8 + 4];
            float4 b0 = *(const float4*)&Bs[cur][kk][tx * 4];
            float af[8] = {a0.x, a0.y, a0.z, a0.w, a1.x, a1.y, a1.z, a1.w};
            float bf[4] = {b0.x, b0.y, b0.z, b0.w};
            #pragma unroll
            for (int mi = 0; mi < 8; mi++)
                #pragma unroll
                for (int ni = 0; ni < 4; ni++)
                    acc[mi][ni] = fmaf(af[mi], bf[ni], acc[mi][ni]);
        }
        __syncthreads();
    }

    int col = bn + tx * 4;
    #pragma unroll
    for (int mi = 0; mi < 8; mi++) {
        int row = bm + ty * 8 + mi;
        float4 v = make_float4(acc[mi][0], acc[mi][1], acc[mi][2], acc[mi][3]);
        *(float4*)(C + (size_t)row * DMODEL + col) = v;
    }
}

// ---------------------------------------------------------------------------
// FC SGEMM: out = Oc(remapped) @ Wfc^T + bias + resid.
// A is the packed attention output Oc[(b*64+d)*512+t][8]; remap on load.
// Per-batch stride = 64*512*8 = 2^18 floats.
// ---------------------------------------------------------------------------
__global__ __launch_bounds__(256, 3) void sgemm_fc(
    const float* __restrict__ Oc, const float* __restrict__ W,
    float* __restrict__ C, const float* __restrict__ bias,
    const float* __restrict__ resid)
{
    const int K = DMODEL;
    __shared__ float As[2][16][128];
    __shared__ float Bs[2][16][64];

    int bm = blockIdx.y * 128;
    int bn = blockIdx.x * 64;
    int tid = threadIdx.x;
    int tx = tid & 15;
    int ty = tid >> 4;

    int ar0 = tid >> 2,         ac0 = (tid & 3) << 2;
    int ar1 = (tid + 256) >> 2, ac1 = ac0;
    int br  = tid >> 2,         bc  = (tid & 3) << 2;

    // remap: token -> (b = tok>>9, t = tok&511); base = b*2^18 + t*8
    int tok0 = bm + ar0, tok1 = bm + ar1;
    size_t base0 = ((size_t)(tok0 >> 9) << 18) + ((size_t)(tok0 & 511) << 3);
    size_t base1 = ((size_t)(tok1 >> 9) << 18) + ((size_t)(tok1 & 511) << 3);
    // + d*4096 + e, where d = col>>3, e = col&7 (col multiple of 4)

    float acc[8][4];
    #pragma unroll
    for (int i = 0; i < 8; i++)
        #pragma unroll
        for (int j = 0; j < 4; j++) acc[i][j] = 0.0f;

    auto aload = [&](size_t base, int col) -> float4 {
        return *(const float4*)(Oc + base + ((size_t)(col >> 3) << 12) + (col & 7));
    };

    float4 ra0, ra1, rb;
    ra0 = aload(base0, ac0);
    ra1 = aload(base1, ac1);
    rb  = *(const float4*)(W + (size_t)(bn + br) * K + bc);
    As[0][ac0 + 0][ar0] = ra0.x; As[0][ac0 + 1][ar0] = ra0.y;
    As[0][ac0 + 2][ar0] = ra0.z; As[0][ac0 + 3][ar0] = ra0.w;
    As[0][ac1 + 0][ar1] = ra1.x; As[0][ac1 + 1][ar1] = ra1.y;
    As[0][ac1 + 2][ar1] = ra1.z; As[0][ac1 + 3][ar1] = ra1.w;
    Bs[0][bc + 0][br] = rb.x; Bs[0][bc + 1][br] = rb.y;
    Bs[0][bc + 2][br] = rb.z; Bs[0][bc + 3][br] = rb.w;
    ra0 = aload(base0, 16 + ac0);
    ra1 = aload(base1, 16 + ac1);
    rb  = *(const float4*)(W + (size_t)(bn + br) * K + 16 + bc);
    __syncthreads();

    const int NCH = K / 16;
    for (int c = 0; c < NCH; c++) {
        int cur = c & 1, nxt = cur ^ 1;
        if (c + 1 < NCH) {
            As[nxt][ac0 + 0][ar0] = ra0.x; As[nxt][ac0 + 1][ar0] = ra0.y;
            As[nxt][ac0 + 2][ar0] = ra0.z; As[nxt][ac0 + 3][ar0] = ra0.w;
            As[nxt][ac1 + 0][ar1] = ra1.x; As[nxt][ac1 + 1][ar1] = ra1.y;
            As[nxt][ac1 + 2][ar1] = ra1.z; As[nxt][ac1 + 3][ar1] = ra1.w;
            Bs[nxt][bc + 0][br] = rb.x; Bs[nxt][bc + 1][br] = rb.y;
            Bs[nxt][bc + 2][br] = rb.z; Bs[nxt][bc + 3][br] = rb.w;
        }
        if (c + 2 < NCH) {
            int k0 = (c + 2) * 16;
            ra0 = aload(base0, k0 + ac0);
            ra1 = aload(base1, k0 + ac1);
            rb  = *(const float4*)(W + (size_t)(bn + br) * K + k0 + bc);
        }
        #pragma unroll
        for (int kk = 0; kk < 16; kk++) {
            float4 a0 = *(const float4*)&As[cur][kk][ty * 8];
            float4 a1 = *(const float4*)&As[cur][kk][ty * 8 + 4];
            float4 b0 = *(const float4*)&Bs[cur][kk][tx * 4];
            float af[8] = {a0.x, a0.y, a0.z, a0.w, a1.x, a1.y, a1.z, a1.w};
            float bf[4] = {b0.x, b0.y, b0.z, b0.w};
            #pragma unroll
            for (int mi = 0; mi < 8; mi++)
                #pragma unroll
                for (int ni = 0; ni < 4; ni++)
                    acc[mi][ni] = fmaf(af[mi], bf[ni], acc[mi][ni]);
        }
        __syncthreads();
    }

    int col = bn + tx * 4;
    float4 bv = *(const float4*)(bias + col);
    #pragma unroll
    for (int mi = 0; mi < 8; mi++) {
        int row = bm + ty * 8 + mi;
        float4 r = *(const float4*)(resid + (size_t)row * DMODEL + col);
        float4 v = make_float4(acc[mi][0] + bv.x + r.x, acc[mi][1] + bv.y + r.y,
                               acc[mi][2] + bv.z + r.z, acc[mi][3] + bv.w + r.w);
        *(float4*)(C + (size_t)row * DMODEL + col) = v;
    }
}

// ---------------------------------------------------------------------------
// Pack: [b*512+t][d*8+e] -> [(b*64+d)*512+t][e]   (coalesced writes)
// ---------------------------------------------------------------------------
__global__ __launch_bounds__(256) void pack_kernel(
    const float* __restrict__ src, float* __restrict__ dst)
{
    int idx = blockIdx.x * 256 + threadIdx.x;    // 0 .. 4M-1
    int e = idx & 7;
    int t = (idx >> 3) & 511;
    int d = (idx >> 12) & 63;
    int b = idx >> 18;
    dst[idx] = src[(size_t)((b << 9) + t) * DMODEL + (d << 3) + e];
}

// ---------------------------------------------------------------------------
// Attention: one block per (b,d); packed inputs; one warp per q-row.
// ---------------------------------------------------------------------------
__global__ __launch_bounds__(512, 2) void attn_kernel(
    const float* __restrict__ Qc, const float* __restrict__ Kc,
    const float* __restrict__ Vc, const float* __restrict__ sim,
    float* __restrict__ attn, float* __restrict__ Oc)
{
    __shared__ float Ks[512][9];
    __shared__ float Vs[512][9];

    int bd = blockIdx.x;
    int tid = threadIdx.x;
    size_t cbase = (size_t)bd * (SEQ * HDIM);   // 4096 floats per (b,d)

    {
        const float4* kp = (const float4*)(Kc + cbase);
        float4 x0 = kp[tid * 2], x1 = kp[tid * 2 + 1];
        Ks[tid][0] = x0.x; Ks[tid][1] = x0.y; Ks[tid][2] = x0.z; Ks[tid][3] = x0.w;
        Ks[tid][4] = x1.x; Ks[tid][5] = x1.y; Ks[tid][6] = x1.z; Ks[tid][7] = x1.w;
        const float4* vp = (const float4*)(Vc + cbase);
        float4 y0 = vp[tid * 2], y1 = vp[tid * 2 + 1];
        Vs[tid][0] = y0.x; Vs[tid][1] = y0.y; Vs[tid][2] = y0.z; Vs[tid][3] = y0.w;
        Vs[tid][4] = y1.x; Vs[tid][5] = y1.y; Vs[tid][6] = y1.z; Vs[tid][7] = y1.w;
    }
    __syncthreads();

    int warp = tid >> 5, lane = tid & 31;
    size_t simbase = (size_t)bd * (SEQ * SEQ);
    const float inv_temp = 0.125f;   // 1/sqrt(64)

    for (int qr = warp; qr < SEQ; qr += 16) {
        const float4* qp = (const float4*)(Qc + cbase + (size_t)qr * HDIM);
        float4 q0 = qp[0], q1 = qp[1];
        float qv[8] = {q0.x, q0.y, q0.z, q0.w, q1.x, q1.y, q1.z, q1.w};

        const float* srow = sim + simbase + (size_t)qr * SEQ;
        float s[16];
        float mx = -3.4e38f;
        #pragma unroll
        for (int i = 0; i < 16; i++) {
            int kk = lane + i * 32;
            float sv = srow[kk];
            float acc = 0.0f;
            #pragma unroll
            for (int e = 0; e < 8; e++) acc = fmaf(qv[e], Ks[kk][e], acc);
            s[i] = fmaf(acc, inv_temp, sv);
            mx = fmaxf(mx, s[i]);
        }
        #pragma unroll
        for (int o = 16; o; o >>= 1) mx = fmaxf(mx, __shfl_xor_sync(0xffffffffu, mx, o));

        float sum = 0.0f;
        float acc8[8] = {0.f, 0.f, 0.f, 0.f, 0.f, 0.f, 0.f, 0.f};
        #pragma unroll
        for (int i = 0; i < 16; i++) {
            float p = __expf(s[i] - mx);
            s[i] = p;
            sum += p;
            int kk = lane + i * 32;
            #pragma unroll
            for (int e = 0; e < 8; e++) acc8[e] = fmaf(p, Vs[kk][e], acc8[e]);
        }
        #pragma unroll
        for (int o = 16; o; o >>= 1) sum += __shfl_xor_sync(0xffffffffu, sum, o);
        float inv = 1.0f / sum;

        if (attn) {
            float* arow = attn + simbase + (size_t)qr * SEQ;
            #pragma unroll
            for (int i = 0; i < 16; i++) arow[lane + i * 32] = s[i] * inv;
        }

        #pragma unroll
        for (int e = 0; e < 8; e++) {
            #pragma unroll
            for (int o = 16; o; o >>= 1)
                acc8[e] += __shfl_xor_sync(0xffffffffu, acc8[e], o);
        }
        if (lane == 0) {
            float* orow = Oc + cbase + (size_t)qr * HDIM;
            float4 o0 = make_float4(acc8[0] * inv, acc8[1] * inv,
                                    acc8[2] * inv, acc8[3] * inv);
            float4 o1 = make_float4(acc8[4] * inv, acc8[5] * inv,
                                    acc8[6] * inv, acc8[7] * inv);
            *(float4*)orow = o0;
            *(float4*)(orow + 4) = o1;
        }
    }
}

// ---------------------------------------------------------------------------
// Launch.  Order matters for profiling: attn is the 6th kernel launch.
// ---------------------------------------------------------------------------
extern "C" void kernel_launch(void* const* d_in, const int* in_sizes, int n_in,
                              void* d_out, int out_size)
{
    const float* q   = (const float*)d_in[0];
    const float* k   = (const float*)d_in[1];
    const float* v   = (const float*)d_in[2];
    const float* sim = (const float*)d_in[3];
    const float* Wq  = (const float*)d_in[4];
    const float* Wk  = (const float*)d_in[5];
    const float* Wv  = (const float*)d_in[6];
    const float* Wfc = (const float*)d_in[7];
    const float* bfc = (const float*)d_in[8];
    const float* lng = (const float*)d_in[9];
    const float* lnb = (const float*)d_in[10];

    float *qn, *Qp, *Kp, *Vp, *Qc, *Kc, *Vc, *Oc;
    cudaGetSymbolAddress((void**)&qn, g_qn);
    cudaGetSymbolAddress((void**)&Qp, g_Qp);
    cudaGetSymbolAddress((void**)&Kp, g_Kp);
    cudaGetSymbolAddress((void**)&Vp, g_Vp);
    cudaGetSymbolAddress((void**)&Qc, g_Qc);
    cudaGetSymbolAddress((void**)&Kc, g_Kc);
    cudaGetSymbolAddress((void**)&Vc, g_Vc);
    cudaGetSymbolAddress((void**)&Oc, g_Oc);

    float* outp = (float*)d_out;
    float* attnp = nullptr;
    const long long NOUT  = (long long)MROWS * DMODEL;
    const long long NATTN = (long long)BATCH * NHEADS * SEQ * SEQ;
    if ((long long)out_size >= NOUT + NATTN) attnp = outp + NOUT;

    // 1) LayerNorm(q)
    ln_kernel<<<MROWS, 256>>>(q, lng, lnb, qn);

    // 2) Batched QKV projections
    dim3 gqkv(DMODEL / 64, MROWS / 128, 3);
    sgemm_qkv<<<gqkv, 256>>>(qn, k, v, Wq, Wk, Wv, Qp, Kp, Vp);

    // 3-5) Pack head-major
    int pblocks = (MROWS * DMODEL) / 256;
    pack_kernel<<<pblocks, 256>>>(Qp, Qc);
    pack_kernel<<<pblocks, 256>>>(Kp, Kc);
    pack_kernel<<<pblocks, 256>>>(Vp, Vc);

    // 6) Attention  (6th launch -> ncu -s 5 -c 1 profiles this one)
    attn_kernel<<<BATCH * NHEADS, 512>>>(Qc, Kc, Vc, sim, attnp, Oc);

    // 7) FC + bias + residual
    dim3 gfc(DMODEL / 64, MROWS / 128);
    sgemm_fc<<<gfc, 256>>>(Oc, Wfc, outp, bfc, q);
}

// round 4
// speedup vs baseline: 1.3182x; 1.3182x over previous
#include <cuda_runtime.h>

#define BATCH   4
#define SEQ     512
#define DMODEL  512
#define MROWS   (BATCH * SEQ)       // 2048
#define NHEADS  64                  // "head" axis = d_k in this module
#define HDIM    8                   // per-head feature dim

// ---------------------------------------------------------------------------
// Scratch (no cudaMalloc allowed)
// ---------------------------------------------------------------------------
__device__ float g_qn[MROWS * DMODEL];
__device__ float g_Qp[MROWS * DMODEL];
__device__ float g_Kp[MROWS * DMODEL];
__device__ float g_Vp[MROWS * DMODEL];
__device__ float g_O [MROWS * DMODEL];

// ---------------------------------------------------------------------------
// LayerNorm over last dim (512), one block per row
// ---------------------------------------------------------------------------
__global__ __launch_bounds__(256) void ln_kernel(
    const float* __restrict__ x, const float* __restrict__ gamma,
    const float* __restrict__ beta, float* __restrict__ out)
{
    int row = blockIdx.x;
    const float* xr = x + (size_t)row * DMODEL;
    int tid = threadIdx.x;
    float a0 = xr[tid];
    float a1 = xr[tid + 256];

    __shared__ float red[8];
    __shared__ float red2[8];
    int warp = tid >> 5, lane = tid & 31;

    float s = a0 + a1;
    #pragma unroll
    for (int o = 16; o; o >>= 1) s += __shfl_xor_sync(0xffffffffu, s, o);
    if (lane == 0) red[warp] = s;
    __syncthreads();
    float mean = (red[0] + red[1] + red[2] + red[3] +
                  red[4] + red[5] + red[6] + red[7]) * (1.0f / 512.0f);

    float d0 = a0 - mean, d1 = a1 - mean;
    float vs = d0 * d0 + d1 * d1;
    #pragma unroll
    for (int o = 16; o; o >>= 1) vs += __shfl_xor_sync(0xffffffffu, vs, o);
    if (lane == 0) red2[warp] = vs;
    __syncthreads();
    float var = (red2[0] + red2[1] + red2[2] + red2[3] +
                 red2[4] + red2[5] + red2[6] + red2[7]) * (1.0f / 512.0f);
    float inv = rsqrtf(var + 1e-6f);

    float* orow = out + (size_t)row * DMODEL;
    orow[tid]       = d0 * inv * gamma[tid]       + beta[tid];
    orow[tid + 256] = d1 * inv * gamma[tid + 256] + beta[tid + 256];
}

// ---------------------------------------------------------------------------
// SGEMM: C[z][2048,512] = A[z][2048,512] @ W[z][512,512]^T (+bias +resid)
// 128x64 tile, BK=16, 256 threads, 8x4 microtile.
// Double-buffered smem; global loads register-staged one chunk ahead.
// Batched over blockIdx.z (pass same pointers 3x for a single GEMM).
// ---------------------------------------------------------------------------
__global__ __launch_bounds__(256, 3) void sgemm_db(
    const float* __restrict__ A0, const float* __restrict__ A1,
    const float* __restrict__ A2,
    const float* __restrict__ W0, const float* __restrict__ W1,
    const float* __restrict__ W2,
    float* __restrict__ C0, float* __restrict__ C1, float* __restrict__ C2,
    const float* __restrict__ bias, const float* __restrict__ resid)
{
    const int K = DMODEL;
    __shared__ float As[2][16][128];
    __shared__ float Bs[2][16][64];

    int z = blockIdx.z;
    const float* A = (z == 0) ? A0 : (z == 1) ? A1 : A2;
    const float* W = (z == 0) ? W0 : (z == 1) ? W1 : W2;
    float*       C = (z == 0) ? C0 : (z == 1) ? C1 : C2;

    int bm = blockIdx.y * 128;
    int bn = blockIdx.x * 64;
    int tid = threadIdx.x;
    int tx = tid & 15;
    int ty = tid >> 4;

    // load geometry: A tile 128x16 = 512 float4 (2/thread); W tile 64x16 = 256 f4 (1/thread)
    int ar0 = tid >> 2,         ac0 = (tid & 3) << 2;
    int ar1 = ar0 + 64;
    int br  = tid >> 2,         bc  = ac0;

    const float* Ap0 = A + (size_t)(bm + ar0) * K + ac0;
    const float* Ap1 = A + (size_t)(bm + ar1) * K + ac0;
    const float* Wp  = W + (size_t)(bn + br)  * K + bc;

    float acc[8][4];
    #pragma unroll
    for (int i = 0; i < 8; i++)
        #pragma unroll
        for (int j = 0; j < 4; j++) acc[i][j] = 0.0f;

    float4 ra0, ra1, rb;

    // chunk 0 -> smem buf 0
    ra0 = *(const float4*)(Ap0);
    ra1 = *(const float4*)(Ap1);
    rb  = *(const float4*)(Wp);
    As[0][ac0 + 0][ar0] = ra0.x; As[0][ac0 + 1][ar0] = ra0.y;
    As[0][ac0 + 2][ar0] = ra0.z; As[0][ac0 + 3][ar0] = ra0.w;
    As[0][ac0 + 0][ar1] = ra1.x; As[0][ac0 + 1][ar1] = ra1.y;
    As[0][ac0 + 2][ar1] = ra1.z; As[0][ac0 + 3][ar1] = ra1.w;
    Bs[0][bc + 0][br] = rb.x; Bs[0][bc + 1][br] = rb.y;
    Bs[0][bc + 2][br] = rb.z; Bs[0][bc + 3][br] = rb.w;
    // stage chunk 1 in regs
    ra0 = *(const float4*)(Ap0 + 16);
    ra1 = *(const float4*)(Ap1 + 16);
    rb  = *(const float4*)(Wp  + 16);
    __syncthreads();

    const int NCH = K / 16;   // 32
    for (int c = 0; c < NCH; c++) {
        int cur = c & 1, nxt = cur ^ 1;
        if (c + 1 < NCH) {
            // commit staged chunk c+1 to the other buffer
            As[nxt][ac0 + 0][ar0] = ra0.x; As[nxt][ac0 + 1][ar0] = ra0.y;
            As[nxt][ac0 + 2][ar0] = ra0.z; As[nxt][ac0 + 3][ar0] = ra0.w;
            As[nxt][ac0 + 0][ar1] = ra1.x; As[nxt][ac0 + 1][ar1] = ra1.y;
            As[nxt][ac0 + 2][ar1] = ra1.z; As[nxt][ac0 + 3][ar1] = ra1.w;
            Bs[nxt][bc + 0][br] = rb.x; Bs[nxt][bc + 1][br] = rb.y;
            Bs[nxt][bc + 2][br] = rb.z; Bs[nxt][bc + 3][br] = rb.w;
            // issue loads for chunk c+2 (clamped; discarded on last use)
            int k0 = (c + 2 < NCH) ? (c + 2) * 16 : (NCH - 1) * 16;
            ra0 = *(const float4*)(Ap0 + k0);
            ra1 = *(const float4*)(Ap1 + k0);
            rb  = *(const float4*)(Wp  + k0);
        }
        #pragma unroll
        for (int kk = 0; kk < 16; kk++) {
            float4 a0 = *(const float4*)&As[cur][kk][ty * 8];
            float4 a1 = *(const float4*)&As[cur][kk][ty * 8 + 4];
            float4 b0 = *(const float4*)&Bs[cur][kk][tx * 4];
            float af[8] = {a0.x, a0.y, a0.z, a0.w, a1.x, a1.y, a1.z, a1.w};
            float bf[4] = {b0.x, b0.y, b0.z, b0.w};
            #pragma unroll
            for (int mi = 0; mi < 8; mi++)
                #pragma unroll
                for (int ni = 0; ni < 4; ni++)
                    acc[mi][ni] = fmaf(af[mi], bf[ni], acc[mi][ni]);
        }
        __syncthreads();
    }

    int col = bn + tx * 4;
    float4 bv = make_float4(0.f, 0.f, 0.f, 0.f);
    if (bias) bv = *(const float4*)(bias + col);
    #pragma unroll
    for (int mi = 0; mi < 8; mi++) {
        int row = bm + ty * 8 + mi;
        float4 v = make_float4(acc[mi][0] + bv.x, acc[mi][1] + bv.y,
                               acc[mi][2] + bv.z, acc[mi][3] + bv.w);
        if (resid) {
            float4 r = *(const float4*)(resid + (size_t)row * DMODEL + col);
            v.x += r.x; v.y += r.y; v.z += r.z; v.w += r.w;
        }
        *(float4*)(C + (size_t)row * DMODEL + col) = v;
    }
}

// ---------------------------------------------------------------------------
// Attention (identical to round-1 passing version).
// One block per (b,d) pair (256 blocks, 512 threads); K/V in padded smem;
// one warp per q-row, shuffle-only reductions.
// ---------------------------------------------------------------------------
__global__ __launch_bounds__(512, 2) void attn_kernel(
    const float* __restrict__ Qp, const float* __restrict__ Kp,
    const float* __restrict__ Vp, const float* __restrict__ sim,
    float* __restrict__ attn, float* __restrict__ O)
{
    __shared__ float Ks[512][9];
    __shared__ float Vs[512][9];

    int bd = blockIdx.x;
    int b = bd >> 6;
    int d = bd & 63;
    int tid = threadIdx.x;

    size_t rowbase = ((size_t)b * SEQ) * DMODEL + (size_t)d * HDIM;

    {
        const float* kp = Kp + rowbase + (size_t)tid * DMODEL;
        float4 x0 = *(const float4*)kp;
        float4 x1 = *(const float4*)(kp + 4);
        Ks[tid][0] = x0.x; Ks[tid][1] = x0.y; Ks[tid][2] = x0.z; Ks[tid][3] = x0.w;
        Ks[tid][4] = x1.x; Ks[tid][5] = x1.y; Ks[tid][6] = x1.z; Ks[tid][7] = x1.w;
        const float* vp = Vp + rowbase + (size_t)tid * DMODEL;
        float4 y0 = *(const float4*)vp;
        float4 y1 = *(const float4*)(vp + 4);
        Vs[tid][0] = y0.x; Vs[tid][1] = y0.y; Vs[tid][2] = y0.z; Vs[tid][3] = y0.w;
        Vs[tid][4] = y1.x; Vs[tid][5] = y1.y; Vs[tid][6] = y1.z; Vs[tid][7] = y1.w;
    }
    __syncthreads();

    int warp = tid >> 5, lane = tid & 31;
    size_t simbase = (size_t)bd * (SEQ * SEQ);
    const float* qpb = Qp + rowbase;
    const float inv_temp = 0.125f;   // 1/sqrt(64)

    for (int qr = warp; qr < SEQ; qr += 16) {
        float qv[8];
        const float* qrow = qpb + (size_t)qr * DMODEL;
        #pragma unroll
        for (int e = 0; e < 8; e++) qv[e] = __ldg(qrow + e);

        const float* srow = sim + simbase + (size_t)qr * SEQ;
        float s[16];
        float mx = -3.4e38f;
        #pragma unroll
        for (int i = 0; i < 16; i++) {
            int kk = lane + i * 32;
            float sv = srow[kk];
            float acc = 0.0f;
            #pragma unroll
            for (int e = 0; e < 8; e++) acc = fmaf(qv[e], Ks[kk][e], acc);
            s[i] = fmaf(acc, inv_temp, sv);
            mx = fmaxf(mx, s[i]);
        }
        #pragma unroll
        for (int o = 16; o; o >>= 1) mx = fmaxf(mx, __shfl_xor_sync(0xffffffffu, mx, o));

        float sum = 0.0f;
        float acc8[8] = {0.f, 0.f, 0.f, 0.f, 0.f, 0.f, 0.f, 0.f};
        #pragma unroll
        for (int i = 0; i < 16; i++) {
            float p = __expf(s[i] - mx);
            s[i] = p;
            sum += p;
            int kk = lane + i * 32;
            #pragma unroll
            for (int e = 0; e < 8; e++) acc8[e] = fmaf(p, Vs[kk][e], acc8[e]);
        }
        #pragma unroll
        for (int o = 16; o; o >>= 1) sum += __shfl_xor_sync(0xffffffffu, sum, o);
        float inv = 1.0f / sum;

        if (attn) {
            float* arow = attn + simbase + (size_t)qr * SEQ;
            #pragma unroll
            for (int i = 0; i < 16; i++) arow[lane + i * 32] = s[i] * inv;
        }

        #pragma unroll
        for (int e = 0; e < 8; e++) {
            #pragma unroll
            for (int o = 16; o; o >>= 1)
                acc8[e] += __shfl_xor_sync(0xffffffffu, acc8[e], o);
        }
        if (lane == 0) {
            float* orow = O + rowbase + (size_t)qr * DMODEL;
            #pragma unroll
            for (int e = 0; e < 8; e++) orow[e] = acc8[e] * inv;
        }
    }
}

// ---------------------------------------------------------------------------
// Launch: ln, qkv(batched), attn, fc  — 4 launches.
// ---------------------------------------------------------------------------
extern "C" void kernel_launch(void* const* d_in, const int* in_sizes, int n_in,
                              void* d_out, int out_size)
{
    const float* q   = (const float*)d_in[0];
    const float* k   = (const float*)d_in[1];
    const float* v   = (const float*)d_in[2];
    const float* sim = (const float*)d_in[3];
    const float* Wq  = (const float*)d_in[4];
    const float* Wk  = (const float*)d_in[5];
    const float* Wv  = (const float*)d_in[6];
    const float* Wfc = (const float*)d_in[7];
    const float* bfc = (const float*)d_in[8];
    const float* lng = (const float*)d_in[9];
    const float* lnb = (const float*)d_in[10];

    float *qn, *Qp, *Kp, *Vp, *O;
    cudaGetSymbolAddress((void**)&qn, g_qn);
    cudaGetSymbolAddress((void**)&Qp, g_Qp);
    cudaGetSymbolAddress((void**)&Kp, g_Kp);
    cudaGetSymbolAddress((void**)&Vp, g_Vp);
    cudaGetSymbolAddress((void**)&O,  g_O);

    float* outp = (float*)d_out;
    float* attnp = nullptr;
    const long long NOUT  = (long long)MROWS * DMODEL;
    const long long NATTN = (long long)BATCH * NHEADS * SEQ * SEQ;
    if ((long long)out_size >= NOUT + NATTN) attnp = outp + NOUT;

    // 1) LayerNorm(q)
    ln_kernel<<<MROWS, 256>>>(q, lng, lnb, qn);

    // 2) Batched QKV projections (384 CTAs, 3/SM)
    dim3 gqkv(DMODEL / 64, MROWS / 128, 3);
    sgemm_db<<<gqkv, 256>>>(qn, k, v, Wq, Wk, Wv, Qp, Kp, Vp,
                            nullptr, nullptr);

    // 3) Attention
    attn_kernel<<<BATCH * NHEADS, 512>>>(Qp, Kp, Vp, sim, attnp, O);

    // 4) FC + bias + residual
    dim3 gfc(DMODEL / 64, MROWS / 128, 1);
    sgemm_db<<<gfc, 256>>>(O, O, O, Wfc, Wfc, Wfc, outp, outp, outp,
                           bfc, q);
}

// round 6
// speedup vs baseline: 1.5819x; 1.2001x over previous
#include <cuda_runtime.h>
#include <cuda_bf16.h>
#include <cstdint>

#define BATCH   4
#define SEQ     512
#define DMODEL  512
#define MROWS   (BATCH * SEQ)       // 2048
#define NHEADS  64                  // "head" axis = d_k in this module
#define HDIM    8                   // per-head feature dim

// ---------------------------------------------------------------------------
// Scratch (no cudaMalloc allowed)
// ---------------------------------------------------------------------------
__device__ float g_qn[MROWS * DMODEL];
__device__ float g_Qp[MROWS * DMODEL];
__device__ float g_Kp[MROWS * DMODEL];
__device__ float g_Vp[MROWS * DMODEL];
__device__ float g_O [MROWS * DMODEL];

// ---------------------------------------------------------------------------
// LayerNorm over last dim (512), one block per row
// ---------------------------------------------------------------------------
__global__ __launch_bounds__(256) void ln_kernel(
    const float* __restrict__ x, const float* __restrict__ gamma,
    const float* __restrict__ beta, float* __restrict__ out)
{
    int row = blockIdx.x;
    const float* xr = x + (size_t)row * DMODEL;
    int tid = threadIdx.x;
    float a0 = xr[tid];
    float a1 = xr[tid + 256];

    __shared__ float red[8];
    __shared__ float red2[8];
    int warp = tid >> 5, lane = tid & 31;

    float s = a0 + a1;
    #pragma unroll
    for (int o = 16; o; o >>= 1) s += __shfl_xor_sync(0xffffffffu, s, o);
    if (lane == 0) red[warp] = s;
    __syncthreads();
    float mean = (red[0] + red[1] + red[2] + red[3] +
                  red[4] + red[5] + red[6] + red[7]) * (1.0f / 512.0f);

    float d0 = a0 - mean, d1 = a1 - mean;
    float vs = d0 * d0 + d1 * d1;
    #pragma unroll
    for (int o = 16; o; o >>= 1) vs += __shfl_xor_sync(0xffffffffu, vs, o);
    if (lane == 0) red2[warp] = vs;
    __syncthreads();
    float var = (red2[0] + red2[1] + red2[2] + red2[3] +
                 red2[4] + red2[5] + red2[6] + red2[7]) * (1.0f / 512.0f);
    float inv = rsqrtf(var + 1e-6f);

    float* orow = out + (size_t)row * DMODEL;
    orow[tid]       = d0 * inv * gamma[tid]       + beta[tid];
    orow[tid + 256] = d1 * inv * gamma[tid + 256] + beta[tid + 256];
}

// ---------------------------------------------------------------------------
// Tensor-core GEMM (bf16 3-pass split, fp32 accumulate):
// C[z][2048,512] = A[z] @ W[z]^T (+bias +resid)
// CTA tile 128x64, BK=16, 256 threads = 8 warps (4m x 2n), warp tile 32x32.
// Each warp: 2x4 grid of m16n8k16 mma, 3 passes (hi*hi, hi*lo, lo*hi).
// Smem stores hi/lo bf16 planes, row stride 24 bf16 (conflict-free frags).
// ---------------------------------------------------------------------------
#define MMA_BF16(d, a, b)                                                    \
    asm volatile(                                                            \
        "mma.sync.aligned.m16n8k16.row.col.f32.bf16.bf16.f32 "              \
        "{%0,%1,%2,%3}, {%4,%5,%6,%7}, {%8,%9}, {%0,%1,%2,%3};"             \
        : "+f"(d[0]), "+f"(d[1]), "+f"(d[2]), "+f"(d[3])                     \
        : "r"(a[0]), "r"(a[1]), "r"(a[2]), "r"(a[3]), "r"(b[0]), "r"(b[1]))

__global__ __launch_bounds__(256) void gemm_bf16x3(
    const float* __restrict__ A0, const float* __restrict__ A1,
    const float* __restrict__ A2,
    const float* __restrict__ W0, const float* __restrict__ W1,
    const float* __restrict__ W2,
    float* __restrict__ C0, float* __restrict__ C1, float* __restrict__ C2,
    const float* __restrict__ bias, const float* __restrict__ resid)
{
    const int K = DMODEL;
    // [buf][plane(hi/lo)][row][k]  row stride 24 bf16 = 12 words
    __shared__ __nv_bfloat16 As[2][2][128][24];
    __shared__ __nv_bfloat16 Bs[2][2][64][24];

    int z = blockIdx.z;
    const float* A = (z == 0) ? A0 : (z == 1) ? A1 : A2;
    const float* W = (z == 0) ? W0 : (z == 1) ? W1 : W2;
    float*       C = (z == 0) ? C0 : (z == 1) ? C1 : C2;

    int bm = blockIdx.y * 128;
    int bn = blockIdx.x * 64;
    int tid = threadIdx.x;
    int wid = tid >> 5, lane = tid & 31;
    int wm = wid >> 1;          // 0..3  (m)
    int wn = wid & 1;           // 0..1  (n)
    int g  = lane >> 2;         // 0..7
    int t  = lane & 3;          // 0..3

    // fill geometry: A tile 128x16 (2 float4/thread), W tile 64x16 (1/thread)
    int ar0 = tid >> 2, ar1 = ar0 + 64, ac = (tid & 3) << 2;

    const float* Ap0 = A + (size_t)(bm + ar0) * K + ac;
    const float* Ap1 = A + (size_t)(bm + ar1) * K + ac;
    const float* Wp  = W + (size_t)(bn + ar0) * K + ac;

    float acc[2][4][4];
    #pragma unroll
    for (int mt = 0; mt < 2; mt++)
        #pragma unroll
        for (int nt = 0; nt < 4; nt++)
            #pragma unroll
            for (int r = 0; r < 4; r++) acc[mt][nt][r] = 0.0f;

    float4 ra0, ra1, rb;

    // split-and-store one float4 into hi/lo bf16 planes
    auto commitA = [&](int buf, int row, float4 v) {
        __nv_bfloat16 hx = __float2bfloat16_rn(v.x);
        __nv_bfloat16 hy = __float2bfloat16_rn(v.y);
        __nv_bfloat16 hz = __float2bfloat16_rn(v.z);
        __nv_bfloat16 hw = __float2bfloat16_rn(v.w);
        __nv_bfloat162 h01; h01.x = hx; h01.y = hy;
        __nv_bfloat162 h23; h23.x = hz; h23.y = hw;
        *(__nv_bfloat162*)&As[buf][0][row][ac]     = h01;
        *(__nv_bfloat162*)&As[buf][0][row][ac + 2] = h23;
        __nv_bfloat162 l01, l23;
        l01.x = __float2bfloat16_rn(v.x - __bfloat162float(hx));
        l01.y = __float2bfloat16_rn(v.y - __bfloat162float(hy));
        l23.x = __float2bfloat16_rn(v.z - __bfloat162float(hz));
        l23.y = __float2bfloat16_rn(v.w - __bfloat162float(hw));
        *(__nv_bfloat162*)&As[buf][1][row][ac]     = l01;
        *(__nv_bfloat162*)&As[buf][1][row][ac + 2] = l23;
    };
    auto commitB = [&](int buf, int row, float4 v) {
        __nv_bfloat16 hx = __float2bfloat16_rn(v.x);
        __nv_bfloat16 hy = __float2bfloat16_rn(v.y);
        __nv_bfloat16 hz = __float2bfloat16_rn(v.z);
        __nv_bfloat16 hw = __float2bfloat16_rn(v.w);
        __nv_bfloat162 h01; h01.x = hx; h01.y = hy;
        __nv_bfloat162 h23; h23.x = hz; h23.y = hw;
        *(__nv_bfloat162*)&Bs[buf][0][row][ac]     = h01;
        *(__nv_bfloat162*)&Bs[buf][0][row][ac + 2] = h23;
        __nv_bfloat162 l01, l23;
        l01.x = __float2bfloat16_rn(v.x - __bfloat162float(hx));
        l01.y = __float2bfloat16_rn(v.y - __bfloat162float(hy));
        l23.x = __float2bfloat16_rn(v.z - __bfloat162float(hz));
        l23.y = __float2bfloat16_rn(v.w - __bfloat162float(hw));
        *(__nv_bfloat162*)&Bs[buf][1][row][ac]     = l01;
        *(__nv_bfloat162*)&Bs[buf][1][row][ac + 2] = l23;
    };

    // chunk 0 -> buf 0
    ra0 = *(const float4*)(Ap0);
    ra1 = *(const float4*)(Ap1);
    rb  = *(const float4*)(Wp);
    commitA(0, ar0, ra0);
    commitA(0, ar1, ra1);
    commitB(0, ar0, rb);
    // stage chunk 1
    ra0 = *(const float4*)(Ap0 + 16);
    ra1 = *(const float4*)(Ap1 + 16);
    rb  = *(const float4*)(Wp  + 16);
    __syncthreads();

    const int NCH = K / 16;   // 32
    for (int c = 0; c < NCH; c++) {
        int cur = c & 1, nxt = cur ^ 1;
        if (c + 1 < NCH) {
            commitA(nxt, ar0, ra0);
            commitA(nxt, ar1, ra1);
            commitB(nxt, ar0, rb);
            int k0 = (c + 2 < NCH) ? (c + 2) * 16 : (NCH - 1) * 16;
            ra0 = *(const float4*)(Ap0 + k0);
            ra1 = *(const float4*)(Ap1 + k0);
            rb  = *(const float4*)(Wp  + k0);
        }

        // fragment loads
        uint32_t ah[2][4], al[2][4], bh[4][2], bl[4][2];
        #pragma unroll
        for (int mt = 0; mt < 2; mt++) {
            int r0 = wm * 32 + mt * 16 + g;
            int r1 = r0 + 8;
            ah[mt][0] = *(const uint32_t*)&As[cur][0][r0][2 * t];
            ah[mt][1] = *(const uint32_t*)&As[cur][0][r1][2 * t];
            ah[mt][2] = *(const uint32_t*)&As[cur][0][r0][8 + 2 * t];
            ah[mt][3] = *(const uint32_t*)&As[cur][0][r1][8 + 2 * t];
            al[mt][0] = *(const uint32_t*)&As[cur][1][r0][2 * t];
            al[mt][1] = *(const uint32_t*)&As[cur][1][r1][2 * t];
            al[mt][2] = *(const uint32_t*)&As[cur][1][r0][8 + 2 * t];
            al[mt][3] = *(const uint32_t*)&As[cur][1][r1][8 + 2 * t];
        }
        #pragma unroll
        for (int nt = 0; nt < 4; nt++) {
            int n = wn * 32 + nt * 8 + g;
            bh[nt][0] = *(const uint32_t*)&Bs[cur][0][n][2 * t];
            bh[nt][1] = *(const uint32_t*)&Bs[cur][0][n][8 + 2 * t];
            bl[nt][0] = *(const uint32_t*)&Bs[cur][1][n][2 * t];
            bl[nt][1] = *(const uint32_t*)&Bs[cur][1][n][8 + 2 * t];
        }

        #pragma unroll
        for (int mt = 0; mt < 2; mt++)
            #pragma unroll
            for (int nt = 0; nt < 4; nt++) {
                MMA_BF16(acc[mt][nt], ah[mt], bh[nt]);
                MMA_BF16(acc[mt][nt], ah[mt], bl[nt]);
                MMA_BF16(acc[mt][nt], al[mt], bh[nt]);
            }
        __syncthreads();
    }

    // epilogue
    #pragma unroll
    for (int mt = 0; mt < 2; mt++) {
        int r0 = bm + wm * 32 + mt * 16 + g;
        int r1 = r0 + 8;
        #pragma unroll
        for (int nt = 0; nt < 4; nt++) {
            int c0 = bn + wn * 32 + nt * 8 + 2 * t;
            float* d = acc[mt][nt];
            float2 bb = make_float2(0.f, 0.f);
            if (bias) bb = *(const float2*)(bias + c0);
            float2 v0 = make_float2(d[0] + bb.x, d[1] + bb.y);
            float2 v1 = make_float2(d[2] + bb.x, d[3] + bb.y);
            if (resid) {
                float2 q0 = *(const float2*)(resid + (size_t)r0 * DMODEL + c0);
                float2 q1 = *(const float2*)(resid + (size_t)r1 * DMODEL + c0);
                v0.x += q0.x; v0.y += q0.y;
                v1.x += q1.x; v1.y += q1.y;
            }
            *(float2*)(C + (size_t)r0 * DMODEL + c0) = v0;
            *(float2*)(C + (size_t)r1 * DMODEL + c0) = v1;
        }
    }
}

// ---------------------------------------------------------------------------
// Attention (unchanged from round-4 passing version).
// ---------------------------------------------------------------------------
__global__ __launch_bounds__(512, 2) void attn_kernel(
    const float* __restrict__ Qp, const float* __restrict__ Kp,
    const float* __restrict__ Vp, const float* __restrict__ sim,
    float* __restrict__ attn, float* __restrict__ O)
{
    __shared__ float Ks[512][9];
    __shared__ float Vs[512][9];

    int bd = blockIdx.x;
    int b = bd >> 6;
    int d = bd & 63;
    int tid = threadIdx.x;

    size_t rowbase = ((size_t)b * SEQ) * DMODEL + (size_t)d * HDIM;

    {
        const float* kp = Kp + rowbase + (size_t)tid * DMODEL;
        float4 x0 = *(const float4*)kp;
        float4 x1 = *(const float4*)(kp + 4);
        Ks[tid][0] = x0.x; Ks[tid][1] = x0.y; Ks[tid][2] = x0.z; Ks[tid][3] = x0.w;
        Ks[tid][4] = x1.x; Ks[tid][5] = x1.y; Ks[tid][6] = x1.z; Ks[tid][7] = x1.w;
        const float* vp = Vp + rowbase + (size_t)tid * DMODEL;
        float4 y0 = *(const float4*)vp;
        float4 y1 = *(const float4*)(vp + 4);
        Vs[tid][0] = y0.x; Vs[tid][1] = y0.y; Vs[tid][2] = y0.z; Vs[tid][3] = y0.w;
        Vs[tid][4] = y1.x; Vs[tid][5] = y1.y; Vs[tid][6] = y1.z; Vs[tid][7] = y1.w;
    }
    __syncthreads();

    int warp = tid >> 5, lane = tid & 31;
    size_t simbase = (size_t)bd * (SEQ * SEQ);
    const float* qpb = Qp + rowbase;
    const float inv_temp = 0.125f;   // 1/sqrt(64)

    for (int qr = warp; qr < SEQ; qr += 16) {
        float qv[8];
        const float* qrow = qpb + (size_t)qr * DMODEL;
        #pragma unroll
        for (int e = 0; e < 8; e++) qv[e] = __ldg(qrow + e);

        const float* srow = sim + simbase + (size_t)qr * SEQ;
        float s[16];
        float mx = -3.4e38f;
        #pragma unroll
        for (int i = 0; i < 16; i++) {
            int kk = lane + i * 32;
            float sv = srow[kk];
            float acc = 0.0f;
            #pragma unroll
            for (int e = 0; e < 8; e++) acc = fmaf(qv[e], Ks[kk][e], acc);
            s[i] = fmaf(acc, inv_temp, sv);
            mx = fmaxf(mx, s[i]);
        }
        #pragma unroll
        for (int o = 16; o; o >>= 1) mx = fmaxf(mx, __shfl_xor_sync(0xffffffffu, mx, o));

        float sum = 0.0f;
        float acc8[8] = {0.f, 0.f, 0.f, 0.f, 0.f, 0.f, 0.f, 0.f};
        #pragma unroll
        for (int i = 0; i < 16; i++) {
            float p = __expf(s[i] - mx);
            s[i] = p;
            sum += p;
            int kk = lane + i * 32;
            #pragma unroll
            for (int e = 0; e < 8; e++) acc8[e] = fmaf(p, Vs[kk][e], acc8[e]);
        }
        #pragma unroll
        for (int o = 16; o; o >>= 1) sum += __shfl_xor_sync(0xffffffffu, sum, o);
        float inv = 1.0f / sum;

        if (attn) {
            float* arow = attn + simbase + (size_t)qr * SEQ;
            #pragma unroll
            for (int i = 0; i < 16; i++) arow[lane + i * 32] = s[i] * inv;
        }

        #pragma unroll
        for (int e = 0; e < 8; e++) {
            #pragma unroll
            for (int o = 16; o; o >>= 1)
                acc8[e] += __shfl_xor_sync(0xffffffffu, acc8[e], o);
        }
        if (lane == 0) {
            float* orow = O + rowbase + (size_t)qr * DMODEL;
            #pragma unroll
            for (int e = 0; e < 8; e++) orow[e] = acc8[e] * inv;
        }
    }
}

// ---------------------------------------------------------------------------
// Launch: ln, qkv(batched, tensor), attn, fc(tensor) — 4 launches.
// ---------------------------------------------------------------------------
extern "C" void kernel_launch(void* const* d_in, const int* in_sizes, int n_in,
                              void* d_out, int out_size)
{
    const float* q   = (const float*)d_in[0];
    const float* k   = (const float*)d_in[1];
    const float* v   = (const float*)d_in[2];
    const float* sim = (const float*)d_in[3];
    const float* Wq  = (const float*)d_in[4];
    const float* Wk  = (const float*)d_in[5];
    const float* Wv  = (const float*)d_in[6];
    const float* Wfc = (const float*)d_in[7];
    const float* bfc = (const float*)d_in[8];
    const float* lng = (const float*)d_in[9];
    const float* lnb = (const float*)d_in[10];

    float *qn, *Qp, *Kp, *Vp, *O;
    cudaGetSymbolAddress((void**)&qn, g_qn);
    cudaGetSymbolAddress((void**)&Qp, g_Qp);
    cudaGetSymbolAddress((void**)&Kp, g_Kp);
    cudaGetSymbolAddress((void**)&Vp, g_Vp);
    cudaGetSymbolAddress((void**)&O,  g_O);

    float* outp = (float*)d_out;
    float* attnp = nullptr;
    const long long NOUT  = (long long)MROWS * DMODEL;
    const long long NATTN = (long long)BATCH * NHEADS * SEQ * SEQ;
    if ((long long)out_size >= NOUT + NATTN) attnp = outp + NOUT;

    // 1) LayerNorm(q)
    ln_kernel<<<MROWS, 256>>>(q, lng, lnb, qn);

    // 2) Batched QKV projections (tensor cores, 384 CTAs)
    dim3 gqkv(DMODEL / 64, MROWS / 128, 3);
    gemm_bf16x3<<<gqkv, 256>>>(qn, k, v, Wq, Wk, Wv, Qp, Kp, Vp,
                               nullptr, nullptr);

    // 3) Attention
    attn_kernel<<<BATCH * NHEADS, 512>>>(Qp, Kp, Vp, sim, attnp, O);

    // 4) FC + bias + residual (tensor cores)
    dim3 gfc(DMODEL / 64, MROWS / 128, 1);
    gemm_bf16x3<<<gfc, 256>>>(O, O, O, Wfc, Wfc, Wfc, outp, outp, outp,
                              bfc, q);
}